// round 12
// baseline (speedup 1.0000x reference)
#include <cuda_runtime.h>
#include <math.h>
#include <stdint.h>

// Problem constants
#define NQPT   20000
#define SSUP   20000
#define NNB    30
#define NKP    15
#define EXT_INV 20.0f
#define KTOT   (NKP * 256)   // 3840
#define COUTC  256
#define SPLITK 4

__device__ float g_scratch[(size_t)NQPT * KTOT];   // tf32-rounded stage1 output
__device__ float g_T[(size_t)SSUP * 288];          // per-support LRF projection
__device__ float g_Wc[(size_t)KTOT * COUTC];       // tf32-rounded weights
__device__ float g_part[(size_t)SPLITK * NQPT * COUTC];  // split-K partials

// ---------------------------------------------------------------------------
// Helpers
// ---------------------------------------------------------------------------
static __device__ __forceinline__ uint32_t smem_u32(const void* p) {
    uint32_t a;
    asm("{ .reg .u64 t; cvta.to.shared.u64 t, %1; cvt.u32.u64 %0, t; }" : "=r"(a) : "l"(p));
    return a;
}
static __device__ __forceinline__ void cpa16(uint32_t s, const void* g) {
    asm volatile("cp.async.cg.shared.global [%0], [%1], 16;" :: "r"(s), "l"(g));
}
#define CP_COMMIT() asm volatile("cp.async.commit_group;" ::: "memory")
#define CP_WAIT1()  asm volatile("cp.async.wait_group 1;"  ::: "memory")
#define CP_WAIT0()  asm volatile("cp.async.wait_group 0;"  ::: "memory")

static __device__ __forceinline__ uint32_t f2tf32(float f) {
    uint32_t u;
    asm("cvt.rna.tf32.f32 %0, %1;" : "=r"(u) : "f"(f));
    return u;
}
static __device__ __forceinline__ void mma16n8k8(float* d, const uint32_t* a, const uint32_t* b) {
    asm volatile(
        "mma.sync.aligned.m16n8k8.row.col.f32.tf32.tf32.f32 "
        "{%0,%1,%2,%3}, {%4,%5,%6,%7}, {%8,%9}, {%0,%1,%2,%3};"
        : "+f"(d[0]), "+f"(d[1]), "+f"(d[2]), "+f"(d[3])
        : "r"(a[0]), "r"(a[1]), "r"(a[2]), "r"(a[3]), "r"(b[0]), "r"(b[1]));
}

// ---------------------------------------------------------------------------
// Prep A: T[spt][(k*3+i)][c] = sum_{s,j} s_lrf[spt][s*9+k*3+j] * W_lrf[(s*9+i*3+j)*32+c]
// ---------------------------------------------------------------------------
__global__ __launch_bounds__(256)
void build_T(const float* __restrict__ s_lrf, const float* __restrict__ W_lrf)
{
    __shared__ float Wsh[36 * 32];
    const int tid = threadIdx.x;
    for (int i = tid; i < 36 * 32; i += 256) Wsh[i] = W_lrf[i];
    __syncthreads();

    const int warp = tid >> 5, lane = tid & 31;
    const int spt = blockIdx.x * 8 + warp;
    if (spt >= SSUP) return;

    const float* sl = s_lrf + (size_t)spt * 36;
    float slr[36];
    #pragma unroll
    for (int i = 0; i < 36; ++i) slr[i] = __ldg(&sl[i]);

    float* Tout = g_T + (size_t)spt * 288;
    #pragma unroll
    for (int k = 0; k < 3; ++k) {
        #pragma unroll
        for (int i = 0; i < 3; ++i) {
            float acc = 0.f;
            #pragma unroll
            for (int s = 0; s < 4; ++s)
                #pragma unroll
                for (int j = 0; j < 3; ++j)
                    acc += slr[s*9 + k*3 + j] * Wsh[(s*9 + i*3 + j) * 32 + lane];
            Tout[(k*3 + i) * 32 + lane] = acc;
        }
    }
}

// Prep B: round weights to tf32 once
__global__ __launch_bounds__(256)
void conv_w(const float* __restrict__ W)
{
    size_t i = (size_t)blockIdx.x * 256 + threadIdx.x;
    if (i < (size_t)KTOT * COUTC)
        g_Wc[i] = __uint_as_float(f2tf32(W[i]));
}

// ---------------------------------------------------------------------------
// Stage 1: per-query block. x rows gathered once into smem via cp.async.
// ---------------------------------------------------------------------------
struct S1 {
    float xs[NNB][128];
    float w[4][NNB][16];
    float lrff[NNB][4][32];
    float ql[36];
    float kp[45];
    float qp[3];
    float bl[32];
    float nb[NNB][3];
    float mask[NNB];
    int   ic[NNB];
};

__global__ __launch_bounds__(256)
void ekp_stage1(const float* __restrict__ q_pts, const float* __restrict__ s_pts,
                const int*   __restrict__ nidx,  const float* __restrict__ x,
                const float* __restrict__ q_lrf, const float* __restrict__ kpt,
                const float* __restrict__ b_lrf)
{
    __shared__ S1 s;
    const int n   = blockIdx.x;
    const int tid = threadIdx.x;

    if (tid < 36)                    s.ql[tid]      = q_lrf[n * 36 + tid];
    if (tid >= 64  && tid < 64+45)   s.kp[tid-64]   = kpt[tid - 64];
    if (tid >= 112 && tid < 115)     s.qp[tid-112]  = q_pts[n * 3 + (tid - 112)];
    if (tid >= 128 && tid < 160)     s.bl[tid-128]  = b_lrf[tid - 128];
    if (tid >= 160 && tid < 160+NNB) {
        int m   = tid - 160;
        int raw = nidx[n * NNB + m];
        bool ok = raw < SSUP;
        s.ic[m]   = ok ? raw : 0;
        s.mask[m] = ok ? 1.0f : 0.0f;
    }
    __syncthreads();

    {
        const uint32_t xsAddr = smem_u32(&s.xs[0][0]);
        #pragma unroll
        for (int e = tid; e < NNB * 32; e += 256) {
            int m = e >> 5, c = e & 31;
            cpa16(xsAddr + (uint32_t)e * 16, x + (size_t)s.ic[m] * 128 + c * 4);
        }
        CP_COMMIT();
    }

    if (tid < NNB) {
        int m = tid;
        int base = s.ic[m] * 3;
        s.nb[m][0] = s_pts[base + 0] - s.qp[0];
        s.nb[m][1] = s_pts[base + 1] - s.qp[1];
        s.nb[m][2] = s_pts[base + 2] - s.qp[2];
    }
    __syncthreads();

    if (tid < 120) {
        int q = tid / 30, m = tid % 30;
        float a0 = 0.f, a1 = 0.f, a2 = 0.f;
        #pragma unroll
        for (int i = 0; i < 3; ++i) {
            float v = s.nb[m][i];
            a0 += v * s.ql[q*9 + i*3 + 0];
            a1 += v * s.ql[q*9 + i*3 + 1];
            a2 += v * s.ql[q*9 + i*3 + 2];
        }
        float msk = s.mask[m];
        #pragma unroll
        for (int k = 0; k < NKP; ++k) {
            float d0 = a0 - s.kp[k*3 + 0];
            float d1 = a1 - s.kp[k*3 + 1];
            float d2 = a2 - s.kp[k*3 + 2];
            float d  = sqrtf(d0*d0 + d1*d1 + d2*d2);
            s.w[q][m][k] = fmaxf(1.0f - d * EXT_INV, 0.0f) * msk;
        }
        s.w[q][m][15] = 0.0f;
    }

    if (tid < 240) {
        int m  = tid >> 3;
        int c4 = tid & 7;
        const float4* Tp = reinterpret_cast<const float4*>(g_T + (size_t)s.ic[m] * 288);
        float acc[4][4];
        #pragma unroll
        for (int q = 0; q < 4; ++q)
            #pragma unroll
            for (int j = 0; j < 4; ++j) acc[q][j] = 0.f;

        #pragma unroll
        for (int ki = 0; ki < 9; ++ki) {
            float4 t = __ldg(&Tp[ki * 8 + c4]);
            #pragma unroll
            for (int q = 0; q < 4; ++q) {
                float f = s.ql[q*9 + ki];
                acc[q][0] += f * t.x;
                acc[q][1] += f * t.y;
                acc[q][2] += f * t.z;
                acc[q][3] += f * t.w;
            }
        }
        float msk = s.mask[m];
        float4 b4 = *reinterpret_cast<const float4*>(&s.bl[c4 * 4]);
        #pragma unroll
        for (int q = 0; q < 4; ++q) {
            float4 v;
            v.x = (acc[q][0] + b4.x) * msk;
            v.y = (acc[q][1] + b4.y) * msk;
            v.z = (acc[q][2] + b4.z) * msk;
            v.w = (acc[q][3] + b4.w) * msk;
            *reinterpret_cast<float4*>(&s.lrff[m][q][c4 * 4]) = v;
        }
    }
    CP_WAIT0();
    __syncthreads();

    {
        int q  = tid >> 6;
        int cg = (tid >> 2) & 15;
        int ks = tid & 3;
        float acc[4][4];
        #pragma unroll
        for (int i = 0; i < 4; ++i)
            #pragma unroll
            for (int j = 0; j < 4; ++j) acc[i][j] = 0.f;

        #pragma unroll 5
        for (int m = 0; m < NNB; ++m) {
            float4 f;
            if (cg < 8) {
                f = *reinterpret_cast<const float4*>(&s.xs[m][(q * 8 + cg) * 4]);
                float msk = s.mask[m];
                f.x *= msk; f.y *= msk; f.z *= msk; f.w *= msk;
            } else {
                f = *reinterpret_cast<const float4*>(&s.lrff[m][q][(cg - 8) * 4]);
            }
            float4 wv = *reinterpret_cast<const float4*>(&s.w[q][m][ks * 4]);
            acc[0][0] += wv.x * f.x; acc[0][1] += wv.x * f.y; acc[0][2] += wv.x * f.z; acc[0][3] += wv.x * f.w;
            acc[1][0] += wv.y * f.x; acc[1][1] += wv.y * f.y; acc[1][2] += wv.y * f.z; acc[1][3] += wv.y * f.w;
            acc[2][0] += wv.z * f.x; acc[2][1] += wv.z * f.y; acc[2][2] += wv.z * f.z; acc[2][3] += wv.z * f.w;
            acc[3][0] += wv.w * f.x; acc[3][1] += wv.w * f.y; acc[3][2] += wv.w * f.z; acc[3][3] += wv.w * f.w;
        }

        float4* outp = reinterpret_cast<float4*>(g_scratch + (size_t)n * KTOT);
        #pragma unroll
        for (int kk = 0; kk < 4; ++kk) {
            int k = ks * 4 + kk;
            if (k < NKP) {
                float4 v;
                v.x = __uint_as_float(f2tf32(acc[kk][0]));
                v.y = __uint_as_float(f2tf32(acc[kk][1]));
                v.z = __uint_as_float(f2tf32(acc[kk][2]));
                v.w = __uint_as_float(f2tf32(acc[kk][3]));
                outp[k * 64 + q * 16 + cg] = v;
            }
        }
    }
}

// ---------------------------------------------------------------------------
// Stage 2: tf32 mma.sync GEMM, round-5 shape + split-K=4 (blockIdx.z).
//   Each CTA computes a 128x128 tile over 30 k-iterations, writes raw fp32
//   partial to g_part[z]. Quarter-tiles (~T/4) pack the wave cleanly.
// ---------------------------------------------------------------------------
#define S2_BM   128
#define S2_BN   128
#define S2_BK   32
#define S2_AST  36
#define S2_BST  132
#define S2_KIT  (KTOT / S2_BK)        // 120
#define S2_KPS  (S2_KIT / SPLITK)     // 30
#define S2_AELT (S2_BM * S2_AST)
#define S2_BELT (S2_BK * S2_BST)
#define S2_SMEM ((3 * (S2_AELT + S2_BELT)) * 4)   // 105984 B

__global__ __launch_bounds__(128, 2)
void ekp_stage2_mma(float* __restrict__ partial)
{
    extern __shared__ float sm[];
    float* Asm = sm;
    float* Bsm = sm + 3 * S2_AELT;

    const int tid  = threadIdx.x;
    const int lane = tid & 31;
    const int wid  = tid >> 5;
    const int wm   = wid & 1;
    const int wn   = wid >> 1;
    const int gid  = lane >> 2;
    const int tig  = lane & 3;
    const int n0   = blockIdx.x * S2_BN;
    const int row0 = blockIdx.y * S2_BM;
    const int kt0  = blockIdx.z * S2_KPS;

    const uint32_t aSm = smem_u32(Asm);
    const uint32_t bSm = smem_u32(Bsm);

    float acc[4][8][4];
    #pragma unroll
    for (int i = 0; i < 4; ++i)
        #pragma unroll
        for (int j = 0; j < 8; ++j)
            #pragma unroll
            for (int l = 0; l < 4; ++l) acc[i][j][l] = 0.f;

    const int aR = tid >> 3, aC = tid & 7;
    const int bR = tid >> 5, bC = tid & 31;

    auto load_tile = [&](int kt, int st) {
        const int k0 = kt * S2_BK;
        const uint32_t aBase = aSm + (uint32_t)(st * S2_AELT) * 4;
        const uint32_t bBase = bSm + (uint32_t)(st * S2_BELT) * 4;
        #pragma unroll
        for (int i = 0; i < 8; ++i) {
            int r = aR + i * 16;
            int grow = row0 + r;
            if (grow > NQPT - 1) grow = NQPT - 1;
            cpa16(aBase + (uint32_t)(r * S2_AST + aC * 4) * 4,
                  g_scratch + (size_t)grow * KTOT + k0 + aC * 4);
        }
        #pragma unroll
        for (int i = 0; i < 8; ++i) {
            int r = bR + i * 4;
            cpa16(bBase + (uint32_t)(r * S2_BST + bC * 4) * 4,
                  g_Wc + (size_t)(k0 + r) * COUTC + n0 + bC * 4);
        }
    };

    load_tile(kt0, 0); CP_COMMIT();
    load_tile(kt0 + 1, 1); CP_COMMIT();

    for (int ki = 0; ki < S2_KPS; ++ki) {
        if (ki + 1 < S2_KPS) { CP_WAIT1(); } else { CP_WAIT0(); }
        __syncthreads();

        const int buf = ki % 3;
        if (ki + 2 < S2_KPS) {
            load_tile(kt0 + ki + 2, (ki + 2) % 3);
            CP_COMMIT();
        }

        const float* Ab = Asm + buf * S2_AELT;
        const float* Bb = Bsm + buf * S2_BELT;

        #pragma unroll
        for (int ks = 0; ks < S2_BK; ks += 8) {
            uint32_t a[4][4];
            #pragma unroll
            for (int mt = 0; mt < 4; ++mt) {
                int mbase = (wm * 64 + mt * 16 + gid) * S2_AST + ks + tig;
                a[mt][0] = __float_as_uint(Ab[mbase]);
                a[mt][1] = __float_as_uint(Ab[mbase + 8 * S2_AST]);
                a[mt][2] = __float_as_uint(Ab[mbase + 4]);
                a[mt][3] = __float_as_uint(Ab[mbase + 8 * S2_AST + 4]);
            }
            uint32_t b[8][2];
            #pragma unroll
            for (int nt = 0; nt < 8; ++nt) {
                int nb = wn * 64 + nt * 8 + gid;
                b[nt][0] = __float_as_uint(Bb[(ks + tig) * S2_BST + nb]);
                b[nt][1] = __float_as_uint(Bb[(ks + tig + 4) * S2_BST + nb]);
            }
            #pragma unroll
            for (int mt = 0; mt < 4; ++mt)
                #pragma unroll
                for (int nt = 0; nt < 8; ++nt)
                    mma16n8k8(acc[mt][nt], a[mt], b[nt]);
        }
        __syncthreads();
    }

    // Store raw fp32 partials (no bias/activation here).
    float* pb = partial + (size_t)blockIdx.z * NQPT * COUTC;
    #pragma unroll
    for (int mt = 0; mt < 4; ++mt) {
        int r0 = row0 + wm * 64 + mt * 16 + gid;
        #pragma unroll
        for (int nt = 0; nt < 8; ++nt) {
            int col = n0 + wn * 64 + nt * 8 + 2 * tig;
            if (r0 < NQPT)
                *reinterpret_cast<float2*>(&pb[(size_t)r0 * COUTC + col]) =
                    make_float2(acc[mt][nt][0], acc[mt][nt][1]);
            if (r0 + 8 < NQPT)
                *reinterpret_cast<float2*>(&pb[(size_t)(r0 + 8) * COUTC + col]) =
                    make_float2(acc[mt][nt][2], acc[mt][nt][3]);
        }
    }
}

// ---------------------------------------------------------------------------
// Reduce: out = LeakyReLU(bias + sum_s partial[s]), vectorized float4.
// ---------------------------------------------------------------------------
__global__ __launch_bounds__(256)
void reduce_out(const float* __restrict__ bias, float* __restrict__ out)
{
    const size_t NF4 = (size_t)NQPT * COUTC / 4;
    size_t i = (size_t)blockIdx.x * 256 + threadIdx.x;
    if (i >= NF4) return;

    const float4* p = reinterpret_cast<const float4*>(g_part);
    float4 v = p[i];
    #pragma unroll
    for (int s = 1; s < SPLITK; ++s) {
        float4 t = p[s * NF4 + i];
        v.x += t.x; v.y += t.y; v.z += t.z; v.w += t.w;
    }
    int col = (int)((i * 4) & (COUTC - 1));
    float4 b = *reinterpret_cast<const float4*>(&bias[col]);
    v.x += b.x; v.y += b.y; v.z += b.z; v.w += b.w;
    v.x = (v.x >= 0.f) ? v.x : 0.1f * v.x;
    v.y = (v.y >= 0.f) ? v.y : 0.1f * v.y;
    v.z = (v.z >= 0.f) ? v.z : 0.1f * v.z;
    v.w = (v.w >= 0.f) ? v.w : 0.1f * v.w;
    reinterpret_cast<float4*>(out)[i] = v;
}

// ---------------------------------------------------------------------------
extern "C" void kernel_launch(void* const* d_in, const int* in_sizes, int n_in,
                              void* d_out, int out_size)
{
    const float* q_pts = (const float*)d_in[0];
    const float* s_pts = (const float*)d_in[1];
    const int*   nind  = (const int*)  d_in[2];
    const float* x     = (const float*)d_in[3];
    const float* q_lrf = (const float*)d_in[4];
    const float* s_lrf = (const float*)d_in[5];
    const float* kpt   = (const float*)d_in[6];
    const float* wts   = (const float*)d_in[7];
    const float* W_lrf = (const float*)d_in[8];
    const float* b_lrf = (const float*)d_in[9];
    const float* bias  = (const float*)d_in[10];
    float* out = (float*)d_out;

    cudaFuncSetAttribute(ekp_stage2_mma, cudaFuncAttributeMaxDynamicSharedMemorySize, S2_SMEM);

    conv_w<<<(KTOT * COUTC + 255) / 256, 256>>>(wts);
    build_T<<<(SSUP + 7) / 8, 256>>>(s_lrf, W_lrf);

    ekp_stage1<<<NQPT, 256>>>(q_pts, s_pts, nind, x, q_lrf, kpt, b_lrf);

    float* d_part;
    cudaGetSymbolAddress((void**)&d_part, g_part);

    dim3 g2(COUTC / S2_BN, (NQPT + S2_BM - 1) / S2_BM, SPLITK);   // (2, 157, 4)
    ekp_stage2_mma<<<g2, 128, S2_SMEM>>>(d_part);

    size_t nf4 = (size_t)NQPT * COUTC / 4;
    reduce_out<<<(unsigned)((nf4 + 255) / 256), 256>>>(bias, out);
}

// round 14
// speedup vs baseline: 1.2034x; 1.2034x over previous
#include <cuda_runtime.h>
#include <math.h>
#include <stdint.h>

// Problem constants
#define NQPT   20000
#define SSUP   20000
#define NNB    30
#define NKP    15
#define EXT_INV 20.0f
#define KTOT   (NKP * 256)   // 3840
#define COUTC  256
#define SPLITK 4

__device__ float g_scratch[(size_t)NQPT * KTOT];   // stage1 output (fp32, tf32-grade)
__device__ float g_T[(size_t)SSUP * 288];          // per-support LRF projection
__device__ float g_Wc[(size_t)KTOT * COUTC];       // tf32-rounded weights
__device__ float g_part[(size_t)SPLITK * NQPT * COUTC];  // split-K partials

// ---------------------------------------------------------------------------
// Helpers
// ---------------------------------------------------------------------------
static __device__ __forceinline__ uint32_t smem_u32(const void* p) {
    uint32_t a;
    asm("{ .reg .u64 t; cvta.to.shared.u64 t, %1; cvt.u32.u64 %0, t; }" : "=r"(a) : "l"(p));
    return a;
}
static __device__ __forceinline__ void cpa16(uint32_t s, const void* g) {
    asm volatile("cp.async.cg.shared.global [%0], [%1], 16;" :: "r"(s), "l"(g));
}
#define CP_COMMIT() asm volatile("cp.async.commit_group;" ::: "memory")
#define CP_WAIT1()  asm volatile("cp.async.wait_group 1;"  ::: "memory")
#define CP_WAIT0()  asm volatile("cp.async.wait_group 0;"  ::: "memory")

static __device__ __forceinline__ uint32_t f2tf32(float f) {
    uint32_t u;
    asm("cvt.rna.tf32.f32 %0, %1;" : "=r"(u) : "f"(f));
    return u;
}
static __device__ __forceinline__ void mma16n8k8(float* d, const uint32_t* a, const uint32_t* b) {
    asm volatile(
        "mma.sync.aligned.m16n8k8.row.col.f32.tf32.tf32.f32 "
        "{%0,%1,%2,%3}, {%4,%5,%6,%7}, {%8,%9}, {%0,%1,%2,%3};"
        : "+f"(d[0]), "+f"(d[1]), "+f"(d[2]), "+f"(d[3])
        : "r"(a[0]), "r"(a[1]), "r"(a[2]), "r"(a[3]), "r"(b[0]), "r"(b[1]));
}

// ---------------------------------------------------------------------------
// Prep A: T[spt][(k*3+i)][c] = sum_{s,j} s_lrf[spt][s*9+k*3+j] * W_lrf[(s*9+i*3+j)*32+c]
// ---------------------------------------------------------------------------
__global__ __launch_bounds__(256)
void build_T(const float* __restrict__ s_lrf, const float* __restrict__ W_lrf)
{
    __shared__ float Wsh[36 * 32];
    const int tid = threadIdx.x;
    for (int i = tid; i < 36 * 32; i += 256) Wsh[i] = W_lrf[i];
    __syncthreads();

    const int warp = tid >> 5, lane = tid & 31;
    const int spt = blockIdx.x * 8 + warp;
    if (spt >= SSUP) return;

    const float* sl = s_lrf + (size_t)spt * 36;
    float slr[36];
    #pragma unroll
    for (int i = 0; i < 36; ++i) slr[i] = __ldg(&sl[i]);

    float* Tout = g_T + (size_t)spt * 288;
    #pragma unroll
    for (int k = 0; k < 3; ++k) {
        #pragma unroll
        for (int i = 0; i < 3; ++i) {
            float acc = 0.f;
            #pragma unroll
            for (int s = 0; s < 4; ++s)
                #pragma unroll
                for (int j = 0; j < 3; ++j)
                    acc += slr[s*9 + k*3 + j] * Wsh[(s*9 + i*3 + j) * 32 + lane];
            Tout[(k*3 + i) * 32 + lane] = acc;
        }
    }
}

// Prep B: round weights to tf32 once
__global__ __launch_bounds__(256)
void conv_w(const float* __restrict__ W)
{
    size_t i = (size_t)blockIdx.x * 256 + threadIdx.x;
    if (i < (size_t)KTOT * COUTC)
        g_Wc[i] = __uint_as_float(f2tf32(W[i]));
}

// ---------------------------------------------------------------------------
// Stage 1: per-query block. Phase D now runs on tensor cores:
//   weighted[q][k15][c64] = wT[q][k][m] @ F[q][m][c]   (M=16,K=32,N=64)
//   8 warps = 4 q-LRFs x 2 column-halves (x half / lrf half), 16 MMAs each.
// ---------------------------------------------------------------------------
#define XS_ST 136   // xs/lrff row stride (floats): 136%32=8 -> conflict-free B frags
#define WT_ST 36    // wT row stride: 36%32=4 -> conflict-free A frags

struct S1 {
    float xs[32][XS_ST];       // 17408 B : gathered x rows (rows 30,31 zero)
    float lrff[32][XS_ST];     // 17408 B : lrff[m][q*32+c'] (rows 30,31 zero)
    float wT[4][16][WT_ST];    //  9216 B : wT[q][k][m], tf32-rounded, zero-padded
    float ql[36];
    float kp[45];
    float qp[3];
    float bl[32];
    float nb[NNB][3];
    float mask[NNB];
    int   ic[NNB];
};

__global__ __launch_bounds__(256)
void ekp_stage1(const float* __restrict__ q_pts, const float* __restrict__ s_pts,
                const int*   __restrict__ nidx,  const float* __restrict__ x,
                const float* __restrict__ q_lrf, const float* __restrict__ kpt,
                const float* __restrict__ b_lrf)
{
    __shared__ S1 s;
    const int n   = blockIdx.x;
    const int tid = threadIdx.x;

    // ---- Phase A: loads + zero padding regions ----
    if (tid < 36)                    s.ql[tid]      = q_lrf[n * 36 + tid];
    if (tid >= 64  && tid < 64+45)   s.kp[tid-64]   = kpt[tid - 64];
    if (tid >= 112 && tid < 115)     s.qp[tid-112]  = q_pts[n * 3 + (tid - 112)];
    if (tid >= 128 && tid < 160)     s.bl[tid-128]  = b_lrf[tid - 128];
    if (tid >= 160 && tid < 160+NNB) {
        int m   = tid - 160;
        int raw = nidx[n * NNB + m];
        bool ok = raw < SSUP;
        s.ic[m]   = ok ? raw : 0;
        s.mask[m] = ok ? 1.0f : 0.0f;
    }
    for (int i = tid; i < 4 * 16 * WT_ST; i += 256) (&s.wT[0][0][0])[i] = 0.f;
    for (int i = tid; i < 2 * XS_ST; i += 256) {
        (&s.xs[30][0])[i]   = 0.f;
        (&s.lrff[30][0])[i] = 0.f;
    }
    __syncthreads();

    // ---- Phase X: async gather of x rows (960 x 16B) ----
    {
        const uint32_t xsAddr = smem_u32(&s.xs[0][0]);
        #pragma unroll
        for (int e = tid; e < NNB * 32; e += 256) {
            int m = e >> 5, c = e & 31;
            cpa16(xsAddr + (uint32_t)(m * (XS_ST * 4) + c * 16),
                  x + (size_t)s.ic[m] * 128 + c * 4);
        }
        CP_COMMIT();
    }

    // ---- Phase B: neighbor offsets ----
    if (tid < NNB) {
        int m = tid;
        int base = s.ic[m] * 3;
        s.nb[m][0] = s_pts[base + 0] - s.qp[0];
        s.nb[m][1] = s_pts[base + 1] - s.qp[1];
        s.nb[m][2] = s_pts[base + 2] - s.qp[2];
    }
    __syncthreads();

    // ---- Phase W: KP weights -> wT[q][k][m] (tf32-rounded, masked) ----
    if (tid < 120) {
        int q = tid / 30, m = tid % 30;
        float a0 = 0.f, a1 = 0.f, a2 = 0.f;
        #pragma unroll
        for (int i = 0; i < 3; ++i) {
            float v = s.nb[m][i];
            a0 += v * s.ql[q*9 + i*3 + 0];
            a1 += v * s.ql[q*9 + i*3 + 1];
            a2 += v * s.ql[q*9 + i*3 + 2];
        }
        float msk = s.mask[m];
        #pragma unroll
        for (int k = 0; k < NKP; ++k) {
            float d0 = a0 - s.kp[k*3 + 0];
            float d1 = a1 - s.kp[k*3 + 1];
            float d2 = a2 - s.kp[k*3 + 2];
            float d  = sqrtf(d0*d0 + d1*d1 + d2*d2);
            float v  = fmaxf(1.0f - d * EXT_INV, 0.0f) * msk;
            s.wT[q][k][m] = __uint_as_float(f2tf32(v));
        }
    }

    // ---- Phase C: lrff[m][q*32+c'] = sum_ki ql[q,ki]*T[ic[m]][ki][c'] + b ----
    if (tid < 240) {
        int m  = tid >> 3;
        int c4 = tid & 7;
        const float4* Tp = reinterpret_cast<const float4*>(g_T + (size_t)s.ic[m] * 288);
        float acc[4][4];
        #pragma unroll
        for (int q = 0; q < 4; ++q)
            #pragma unroll
            for (int j = 0; j < 4; ++j) acc[q][j] = 0.f;

        #pragma unroll
        for (int ki = 0; ki < 9; ++ki) {
            float4 t = __ldg(&Tp[ki * 8 + c4]);
            #pragma unroll
            for (int q = 0; q < 4; ++q) {
                float f = s.ql[q*9 + ki];
                acc[q][0] += f * t.x;
                acc[q][1] += f * t.y;
                acc[q][2] += f * t.z;
                acc[q][3] += f * t.w;
            }
        }
        float msk = s.mask[m];
        float4 b4 = *reinterpret_cast<const float4*>(&s.bl[c4 * 4]);
        #pragma unroll
        for (int q = 0; q < 4; ++q) {
            float4 v;
            v.x = __uint_as_float(f2tf32((acc[q][0] + b4.x) * msk));
            v.y = __uint_as_float(f2tf32((acc[q][1] + b4.y) * msk));
            v.z = __uint_as_float(f2tf32((acc[q][2] + b4.z) * msk));
            v.w = __uint_as_float(f2tf32((acc[q][3] + b4.w) * msk));
            *reinterpret_cast<float4*>(&s.lrff[m][q * 32 + c4 * 4]) = v;
        }
    }
    CP_WAIT0();
    __syncthreads();

    // ---- Phase D (tensor): per warp, one 16x32 @ 32x32 tf32 MMA tile ----
    {
        const int warp = tid >> 5;
        const int lane = tid & 31;
        const int gid  = lane >> 2;     // 0..7
        const int tig  = lane & 3;      // 0..3
        const int q    = warp >> 1;     // 0..3
        const int half = warp & 1;      // 0 = x half, 1 = lrf half
        const float* Bb = half ? &s.lrff[0][q * 32] : &s.xs[0][q * 32];
        const float* Ab = &s.wT[q][0][0];

        float acc[4][4];
        #pragma unroll
        for (int i = 0; i < 4; ++i)
            #pragma unroll
            for (int j = 0; j < 4; ++j) acc[i][j] = 0.f;

        #pragma unroll
        for (int ks = 0; ks < 32; ks += 8) {
            uint32_t a[4];
            a[0] = __float_as_uint(Ab[gid * WT_ST + ks + tig]);
            a[1] = __float_as_uint(Ab[(gid + 8) * WT_ST + ks + tig]);
            a[2] = __float_as_uint(Ab[gid * WT_ST + ks + tig + 4]);
            a[3] = __float_as_uint(Ab[(gid + 8) * WT_ST + ks + tig + 4]);
            uint32_t b[4][2];
            #pragma unroll
            for (int nt = 0; nt < 4; ++nt) {
                int nb = nt * 8 + gid;
                b[nt][0] = __float_as_uint(Bb[(ks + tig) * XS_ST + nb]);
                b[nt][1] = __float_as_uint(Bb[(ks + tig + 4) * XS_ST + nb]);
            }
            #pragma unroll
            for (int nt = 0; nt < 4; ++nt)
                mma16n8k8(acc[nt], a, b[nt]);
        }

        // Store: rows k=gid and k=gid+8 (skip pad row 15), cols per nt.
        float* outp = g_scratch + (size_t)n * KTOT;
        #pragma unroll
        for (int nt = 0; nt < 4; ++nt) {
            int col = q * 64 + half * 32 + nt * 8 + 2 * tig;
            *reinterpret_cast<float2*>(&outp[gid * 256 + col]) =
                make_float2(acc[nt][0], acc[nt][1]);
            if (gid < 7)
                *reinterpret_cast<float2*>(&outp[(gid + 8) * 256 + col]) =
                    make_float2(acc[nt][2], acc[nt][3]);
        }
    }
}

// ---------------------------------------------------------------------------
// Stage 2: tf32 mma.sync GEMM, round-5 shape + split-K=4 (unchanged, proven).
// ---------------------------------------------------------------------------
#define S2_BM   128
#define S2_BN   128
#define S2_BK   32
#define S2_AST  36
#define S2_BST  132
#define S2_KIT  (KTOT / S2_BK)        // 120
#define S2_KPS  (S2_KIT / SPLITK)     // 30
#define S2_AELT (S2_BM * S2_AST)
#define S2_BELT (S2_BK * S2_BST)
#define S2_SMEM ((3 * (S2_AELT + S2_BELT)) * 4)   // 105984 B

__global__ __launch_bounds__(128, 2)
void ekp_stage2_mma(float* __restrict__ partial)
{
    extern __shared__ float sm[];
    float* Asm = sm;
    float* Bsm = sm + 3 * S2_AELT;

    const int tid  = threadIdx.x;
    const int lane = tid & 31;
    const int wid  = tid >> 5;
    const int wm   = wid & 1;
    const int wn   = wid >> 1;
    const int gid  = lane >> 2;
    const int tig  = lane & 3;
    const int n0   = blockIdx.x * S2_BN;
    const int row0 = blockIdx.y * S2_BM;
    const int kt0  = blockIdx.z * S2_KPS;

    const uint32_t aSm = smem_u32(Asm);
    const uint32_t bSm = smem_u32(Bsm);

    float acc[4][8][4];
    #pragma unroll
    for (int i = 0; i < 4; ++i)
        #pragma unroll
        for (int j = 0; j < 8; ++j)
            #pragma unroll
            for (int l = 0; l < 4; ++l) acc[i][j][l] = 0.f;

    const int aR = tid >> 3, aC = tid & 7;
    const int bR = tid >> 5, bC = tid & 31;

    auto load_tile = [&](int kt, int st) {
        const int k0 = kt * S2_BK;
        const uint32_t aBase = aSm + (uint32_t)(st * S2_AELT) * 4;
        const uint32_t bBase = bSm + (uint32_t)(st * S2_BELT) * 4;
        #pragma unroll
        for (int i = 0; i < 8; ++i) {
            int r = aR + i * 16;
            int grow = row0 + r;
            if (grow > NQPT - 1) grow = NQPT - 1;
            cpa16(aBase + (uint32_t)(r * S2_AST + aC * 4) * 4,
                  g_scratch + (size_t)grow * KTOT + k0 + aC * 4);
        }
        #pragma unroll
        for (int i = 0; i < 8; ++i) {
            int r = bR + i * 4;
            cpa16(bBase + (uint32_t)(r * S2_BST + bC * 4) * 4,
                  g_Wc + (size_t)(k0 + r) * COUTC + n0 + bC * 4);
        }
    };

    load_tile(kt0, 0); CP_COMMIT();
    load_tile(kt0 + 1, 1); CP_COMMIT();

    for (int ki = 0; ki < S2_KPS; ++ki) {
        if (ki + 1 < S2_KPS) { CP_WAIT1(); } else { CP_WAIT0(); }
        __syncthreads();

        const int buf = ki % 3;
        if (ki + 2 < S2_KPS) {
            load_tile(kt0 + ki + 2, (ki + 2) % 3);
            CP_COMMIT();
        }

        const float* Ab = Asm + buf * S2_AELT;
        const float* Bb = Bsm + buf * S2_BELT;

        #pragma unroll
        for (int ks = 0; ks < S2_BK; ks += 8) {
            uint32_t a[4][4];
            #pragma unroll
            for (int mt = 0; mt < 4; ++mt) {
                int mbase = (wm * 64 + mt * 16 + gid) * S2_AST + ks + tig;
                a[mt][0] = __float_as_uint(Ab[mbase]);
                a[mt][1] = __float_as_uint(Ab[mbase + 8 * S2_AST]);
                a[mt][2] = __float_as_uint(Ab[mbase + 4]);
                a[mt][3] = __float_as_uint(Ab[mbase + 8 * S2_AST + 4]);
            }
            uint32_t b[8][2];
            #pragma unroll
            for (int nt = 0; nt < 8; ++nt) {
                int nb = wn * 64 + nt * 8 + gid;
                b[nt][0] = __float_as_uint(Bb[(ks + tig) * S2_BST + nb]);
                b[nt][1] = __float_as_uint(Bb[(ks + tig + 4) * S2_BST + nb]);
            }
            #pragma unroll
            for (int mt = 0; mt < 4; ++mt)
                #pragma unroll
                for (int nt = 0; nt < 8; ++nt)
                    mma16n8k8(acc[mt][nt], a[mt], b[nt]);
        }
        __syncthreads();
    }

    // Store raw fp32 partials (no bias/activation here).
    float* pb = partial + (size_t)blockIdx.z * NQPT * COUTC;
    #pragma unroll
    for (int mt = 0; mt < 4; ++mt) {
        int r0 = row0 + wm * 64 + mt * 16 + gid;
        #pragma unroll
        for (int nt = 0; nt < 8; ++nt) {
            int col = n0 + wn * 64 + nt * 8 + 2 * tig;
            if (r0 < NQPT)
                *reinterpret_cast<float2*>(&pb[(size_t)r0 * COUTC + col]) =
                    make_float2(acc[mt][nt][0], acc[mt][nt][1]);
            if (r0 + 8 < NQPT)
                *reinterpret_cast<float2*>(&pb[(size_t)(r0 + 8) * COUTC + col]) =
                    make_float2(acc[mt][nt][2], acc[mt][nt][3]);
        }
    }
}

// ---------------------------------------------------------------------------
// Reduce: out = LeakyReLU(bias + sum_s partial[s]), vectorized float4.
// ---------------------------------------------------------------------------
__global__ __launch_bounds__(256)
void reduce_out(const float* __restrict__ bias, float* __restrict__ out)
{
    const size_t NF4 = (size_t)NQPT * COUTC / 4;
    size_t i = (size_t)blockIdx.x * 256 + threadIdx.x;
    if (i >= NF4) return;

    const float4* p = reinterpret_cast<const float4*>(g_part);
    float4 v = p[i];
    #pragma unroll
    for (int s = 1; s < SPLITK; ++s) {
        float4 t = p[s * NF4 + i];
        v.x += t.x; v.y += t.y; v.z += t.z; v.w += t.w;
    }
    int col = (int)((i * 4) & (COUTC - 1));
    float4 b = *reinterpret_cast<const float4*>(&bias[col]);
    v.x += b.x; v.y += b.y; v.z += b.z; v.w += b.w;
    v.x = (v.x >= 0.f) ? v.x : 0.1f * v.x;
    v.y = (v.y >= 0.f) ? v.y : 0.1f * v.y;
    v.z = (v.z >= 0.f) ? v.z : 0.1f * v.z;
    v.w = (v.w >= 0.f) ? v.w : 0.1f * v.w;
    reinterpret_cast<float4*>(out)[i] = v;
}

// ---------------------------------------------------------------------------
extern "C" void kernel_launch(void* const* d_in, const int* in_sizes, int n_in,
                              void* d_out, int out_size)
{
    const float* q_pts = (const float*)d_in[0];
    const float* s_pts = (const float*)d_in[1];
    const int*   nind  = (const int*)  d_in[2];
    const float* x     = (const float*)d_in[3];
    const float* q_lrf = (const float*)d_in[4];
    const float* s_lrf = (const float*)d_in[5];
    const float* kpt   = (const float*)d_in[6];
    const float* wts   = (const float*)d_in[7];
    const float* W_lrf = (const float*)d_in[8];
    const float* b_lrf = (const float*)d_in[9];
    const float* bias  = (const float*)d_in[10];
    float* out = (float*)d_out;

    cudaFuncSetAttribute(ekp_stage2_mma, cudaFuncAttributeMaxDynamicSharedMemorySize, S2_SMEM);

    conv_w<<<(KTOT * COUTC + 255) / 256, 256>>>(wts);
    build_T<<<(SSUP + 7) / 8, 256>>>(s_lrf, W_lrf);

    ekp_stage1<<<NQPT, 256>>>(q_pts, s_pts, nind, x, q_lrf, kpt, b_lrf);

    float* d_part;
    cudaGetSymbolAddress((void**)&d_part, g_part);

    dim3 g2(COUTC / S2_BN, (NQPT + S2_BM - 1) / S2_BM, SPLITK);   // (2, 157, 4)
    ekp_stage2_mma<<<g2, 128, S2_SMEM>>>(d_part);

    size_t nf4 = (size_t)NQPT * COUTC / 4;
    reduce_out<<<(unsigned)((nf4 + 255) / 256), 256>>>(bias, out);
}